// round 1
// baseline (speedup 1.0000x reference)
#include <cuda_runtime.h>
#include <stdint.h>

#define M_ROWS 16384
#define N_CODES 8192
#define KDIM 256
#define BM 64
#define BN 128
#define BK 32
#define Q_ELEMS (M_ROWS * KDIM)   // 4194304

// persistent scratch (no allocations allowed)
__device__ unsigned long long g_best[M_ROWS];
__device__ float g_partial[M_ROWS];
__device__ float g_enorm[N_CODES];

__device__ __forceinline__ unsigned long long fma2(unsigned long long a,
                                                   unsigned long long b,
                                                   unsigned long long c) {
    unsigned long long d;
    asm("fma.rn.f32x2 %0, %1, %2, %3;" : "=l"(d) : "l"(a), "l"(b), "l"(c));
    return d;
}

__device__ __forceinline__ unsigned long long dup2(float a) {
    unsigned long long d;
    asm("mov.b64 %0, {%1, %1};" : "=l"(d) : "f"(a));
    return d;
}

__device__ __forceinline__ unsigned long long umin64(unsigned long long a,
                                                     unsigned long long b) {
    return a < b ? a : b;
}

// float -> order-preserving uint32 (ascending)
__device__ __forceinline__ unsigned fkey(float f) {
    unsigned u = __float_as_uint(f);
    return (u & 0x80000000u) ? ~u : (u | 0x80000000u);
}

__global__ void init_kernel() {
    int i = blockIdx.x * blockDim.x + threadIdx.x;
    if (i < M_ROWS) g_best[i] = ~0ull;
}

__global__ void enorm_kernel(const float* __restrict__ emb) {
    int row = blockIdx.x * (blockDim.x >> 5) + (threadIdx.x >> 5);
    int lane = threadIdx.x & 31;
    if (row >= N_CODES) return;
    const float* e = emb + (size_t)row * KDIM;
    float s = 0.f;
#pragma unroll
    for (int c = lane; c < KDIM; c += 32) {
        float v = e[c];
        s = fmaf(v, v, s);
    }
#pragma unroll
    for (int o = 16; o; o >>= 1) s += __shfl_xor_sync(0xffffffffu, s, o);
    if (lane == 0) g_enorm[row] = s;
}

// Distance-argmin GEMM: each CTA does a 64x128 tile of dot(z, e) over K=256,
// epilogue folds argmin of (||e||^2 - 2*dot) into a packed-u64 atomicMin.
__global__ __launch_bounds__(256) void vq_argmin_kernel(const float* __restrict__ z,
                                                        const float* __restrict__ emb) {
    __shared__ __align__(16) float As[BK][BM + 4];
    __shared__ __align__(16) float Bs[BK][BN + 4];
    __shared__ unsigned long long red[BM][16];

    const int tid = threadIdx.x;
    const int tx = tid & 15;   // n direction: 8 codes per thread
    const int ty = tid >> 4;   // m direction: 4 rows per thread
    const int bm = blockIdx.y * BM;
    const int bn = blockIdx.x * BN;

    unsigned long long acc[4][4];
#pragma unroll
    for (int i = 0; i < 4; i++)
#pragma unroll
        for (int p = 0; p < 4; p++) acc[i][p] = 0ull;

    for (int k0 = 0; k0 < KDIM; k0 += BK) {
        // stage A tile (64 x 32), transposed to k-major
#pragma unroll
        for (int i = 0; i < 2; i++) {
            int lin = tid + i * 256;           // 0..511 float4s
            int m = lin >> 3;                  // row within tile
            int kq = (lin & 7) << 2;           // k offset (x4)
            float4 v = *(const float4*)(z + (size_t)(bm + m) * KDIM + k0 + kq);
            As[kq + 0][m] = v.x;
            As[kq + 1][m] = v.y;
            As[kq + 2][m] = v.z;
            As[kq + 3][m] = v.w;
        }
        // stage B tile (128 x 32), transposed to k-major
#pragma unroll
        for (int i = 0; i < 4; i++) {
            int lin = tid + i * 256;           // 0..1023 float4s
            int n = lin >> 3;
            int kq = (lin & 7) << 2;
            float4 v = *(const float4*)(emb + (size_t)(bn + n) * KDIM + k0 + kq);
            Bs[kq + 0][n] = v.x;
            Bs[kq + 1][n] = v.y;
            Bs[kq + 2][n] = v.z;
            Bs[kq + 3][n] = v.w;
        }
        __syncthreads();

#pragma unroll
        for (int k = 0; k < BK; k++) {
            float4 av = *(const float4*)&As[k][ty << 2];
            ulonglong2 b01 = *(const ulonglong2*)&Bs[k][tx << 3];
            ulonglong2 b23 = *(const ulonglong2*)&Bs[k][(tx << 3) + 4];
            unsigned long long a0 = dup2(av.x);
            unsigned long long a1 = dup2(av.y);
            unsigned long long a2 = dup2(av.z);
            unsigned long long a3 = dup2(av.w);

            acc[0][0] = fma2(a0, b01.x, acc[0][0]);
            acc[0][1] = fma2(a0, b01.y, acc[0][1]);
            acc[0][2] = fma2(a0, b23.x, acc[0][2]);
            acc[0][3] = fma2(a0, b23.y, acc[0][3]);

            acc[1][0] = fma2(a1, b01.x, acc[1][0]);
            acc[1][1] = fma2(a1, b01.y, acc[1][1]);
            acc[1][2] = fma2(a1, b23.x, acc[1][2]);
            acc[1][3] = fma2(a1, b23.y, acc[1][3]);

            acc[2][0] = fma2(a2, b01.x, acc[2][0]);
            acc[2][1] = fma2(a2, b01.y, acc[2][1]);
            acc[2][2] = fma2(a2, b23.x, acc[2][2]);
            acc[2][3] = fma2(a2, b23.y, acc[2][3]);

            acc[3][0] = fma2(a3, b01.x, acc[3][0]);
            acc[3][1] = fma2(a3, b01.y, acc[3][1]);
            acc[3][2] = fma2(a3, b23.x, acc[3][2]);
            acc[3][3] = fma2(a3, b23.y, acc[3][3]);
        }
        __syncthreads();
    }

    // epilogue: per-thread argmin over its 8 codes x 4 rows
    const int n_base = bn + (tx << 3);
    float en[8];
#pragma unroll
    for (int j = 0; j < 8; j++) en[j] = g_enorm[n_base + j];

#pragma unroll
    for (int i = 0; i < 4; i++) {
        unsigned long long best = ~0ull;
#pragma unroll
        for (int p = 0; p < 4; p++) {
            float lo = __uint_as_float((unsigned)(acc[i][p] & 0xFFFFFFFFull));
            float hi = __uint_as_float((unsigned)(acc[i][p] >> 32));
            int j = p << 1;
            float d0 = en[j] - 2.f * lo;
            float d1 = en[j + 1] - 2.f * hi;
            unsigned long long key0 =
                ((unsigned long long)fkey(d0) << 32) | (unsigned)(n_base + j);
            unsigned long long key1 =
                ((unsigned long long)fkey(d1) << 32) | (unsigned)(n_base + j + 1);
            best = umin64(best, umin64(key0, key1));
        }
        red[(ty << 2) + i][tx] = best;
    }
    __syncthreads();

    if (tid < BM) {
        unsigned long long best = red[tid][0];
#pragma unroll
        for (int t = 1; t < 16; t++) best = umin64(best, red[tid][t]);
        atomicMin(&g_best[bm + tid], best);
    }
}

// Gather quantized rows, write output + indices, per-row loss partial (deterministic)
__global__ void gather_kernel(const float* __restrict__ z,
                              const float* __restrict__ emb,
                              float* __restrict__ out, int has_extra) {
    int row = blockIdx.x;
    int tid = threadIdx.x;  // 256 threads = KDIM
    unsigned long long key = g_best[row];
    int idx = (int)(key & 0xFFFFFFFFull);

    float q = emb[(size_t)idx * KDIM + tid];
    float zv = z[(size_t)row * KDIM + tid];
    out[(size_t)row * KDIM + tid] = q;

    float dfl = q - zv;
    __shared__ float sh[256];
    sh[tid] = dfl * dfl;
    __syncthreads();
#pragma unroll
    for (int o = 128; o; o >>= 1) {
        if (tid < o) sh[tid] += sh[tid + o];
        __syncthreads();
    }
    if (tid == 0) {
        g_partial[row] = sh[0];
        if (has_extra) out[Q_ELEMS + 1 + row] = (float)idx;
    }
}

__global__ void finalize_kernel(float* __restrict__ out, int has_extra) {
    if (!has_extra) return;
    __shared__ float sh[256];
    int tid = threadIdx.x;
    float s = 0.f;
    for (int i = tid; i < M_ROWS; i += 256) s += g_partial[i];
    sh[tid] = s;
    __syncthreads();
#pragma unroll
    for (int o = 128; o; o >>= 1) {
        if (tid < o) sh[tid] += sh[tid + o];
        __syncthreads();
    }
    if (tid == 0) out[Q_ELEMS] = 1.25f * sh[0] / (float)Q_ELEMS;
}

extern "C" void kernel_launch(void* const* d_in, const int* in_sizes, int n_in,
                              void* d_out, int out_size) {
    // identify inputs by size: z has 16*1024*256 elems, embedding 8192*256
    const float* z;
    const float* emb;
    if (in_sizes[0] == M_ROWS * KDIM) {
        z = (const float*)d_in[0];
        emb = (const float*)d_in[1];
    } else {
        z = (const float*)d_in[1];
        emb = (const float*)d_in[0];
    }
    float* out = (float*)d_out;
    int has_extra = (out_size >= Q_ELEMS + 1 + M_ROWS) ? 1 : 0;

    init_kernel<<<M_ROWS / 256, 256>>>();
    enorm_kernel<<<N_CODES / 8, 256>>>(emb);

    dim3 grid(N_CODES / BN, M_ROWS / BM);  // (64, 256)
    vq_argmin_kernel<<<grid, 256>>>(z, emb);

    gather_kernel<<<M_ROWS, 256>>>(z, emb, out, has_extra);
    finalize_kernel<<<1, 256>>>(out, has_extra);
}

// round 3
// speedup vs baseline: 5.6982x; 5.6982x over previous
#include <cuda_runtime.h>
#include <stdint.h>

#define M_ROWS 16384
#define N_CODES 8192
#define KDIM 256
#define Q_ELEMS (M_ROWS * KDIM)

#define MT 128
#define NT 128
#define BK 32
#define STAGES 3
#define CHUNKS 24   // 3 emulation phases * (256/32)

// tcgen05-path smem layout
#define TC_MBAR_OFF 64
#define TC_EN_OFF 512
#define TC_STAGE0 1024
#define TC_STAGE_BYTES 32768          // A 16KB + B 16KB
#define TC_TOTAL (TC_STAGE0 + STAGES * TC_STAGE_BYTES)

// fallback-path smem layout (padded row-major, stride 36 floats)
#define FB_LDA 36
#define FB_TILE_FLOATS (128 * FB_LDA)
#define FB_STAGE_BYTES (2 * FB_TILE_FLOATS * 4)   // 36864
#define FB_STAGE0 512
#define FB_TOTAL (FB_STAGE0 + STAGES * FB_STAGE_BYTES)

#define SMEM_LAUNCH (FB_TOTAL > TC_TOTAL ? FB_TOTAL : TC_TOTAL)

// ------------------------- persistent scratch -------------------------
__device__ unsigned long long g_best[M_ROWS];
__device__ float g_partial[M_ROWS];
__device__ float g_enorm[N_CODES];
__device__ float g_zhi[M_ROWS * KDIM];
__device__ float g_zlo[M_ROWS * KDIM];
__device__ float g_ehi[N_CODES * KDIM];
__device__ float g_elo[N_CODES * KDIM];

// ------------------------- common helpers -------------------------
__device__ __forceinline__ uint32_t smem_u32(const void* p) {
    uint32_t a;
    asm("{ .reg .u64 t; cvta.to.shared.u64 t, %1; cvt.u32.u64 %0, t; }"
        : "=r"(a) : "l"(p));
    return a;
}

__device__ __forceinline__ void cp16(uint32_t dst, const void* src) {
    asm volatile("cp.async.cg.shared.global [%0], [%1], 16;" :: "r"(dst), "l"(src));
}
__device__ __forceinline__ void cp_commit() { asm volatile("cp.async.commit_group;"); }
__device__ __forceinline__ void cp_wait1() { asm volatile("cp.async.wait_group 1;" ::: "memory"); }
__device__ __forceinline__ void cp_wait0() { asm volatile("cp.async.wait_group 0;" ::: "memory"); }

__device__ __forceinline__ unsigned fkey(float f) {
    unsigned u = __float_as_uint(f);
    return (u & 0x80000000u) ? ~u : (u | 0x80000000u);
}
__device__ __forceinline__ unsigned long long umin64(unsigned long long a,
                                                     unsigned long long b) {
    return a < b ? a : b;
}
__device__ __forceinline__ float tf32_rna(float x) {
    uint32_t b;
    asm("cvt.rna.tf32.f32 %0, %1;" : "=r"(b) : "f"(x));
    return __uint_as_float(b);
}

// ------------------------- tcgen05 helpers (arch-specific only) -------------------------
#if defined(__CUDA_ARCH_FEAT_SM103_ALL)

__device__ __forceinline__ uint32_t elect_one() {
    uint32_t pred;
    asm volatile(
        "{\n\t.reg .pred p;\n\telect.sync _|p, 0xFFFFFFFF;\n\t"
        "selp.b32 %0, 1, 0, p;\n\t}" : "=r"(pred));
    return pred;
}

#define MBARRIER_INIT(addr, cnt) \
    asm volatile("mbarrier.init.shared.b64 [%0], %1;" :: "r"(addr), "r"(cnt) : "memory")

#define MBARRIER_WAIT_PARITY(mbar, parity) do {                                   \
    uint32_t _m = (mbar); uint32_t _p = (parity); uint32_t _done;                 \
    asm volatile("{\n\t.reg .pred p;\n\t"                                         \
        "mbarrier.try_wait.parity.acquire.cta.shared::cta.b64 p, [%1], %2;\n\t"   \
        "selp.b32 %0, 1, 0, p;\n\t}" : "=r"(_done) : "r"(_m), "r"(_p) : "memory");\
    if (!_done) {                                                                 \
        asm volatile("{\n\t.reg .pred P1;\n\t"                                    \
            "WAIT_LOOP_%=:\n\t"                                                   \
            "mbarrier.try_wait.parity.acquire.cta.shared::cta.b64 P1, [%0], %1, 0x989680;\n\t" \
            "@P1 bra.uni WAIT_DONE_%=;\n\t"                                       \
            "bra.uni WAIT_LOOP_%=;\n\t"                                           \
            "WAIT_DONE_%=:\n\t}" :: "r"(_m), "r"(_p) : "memory");                 \
    }                                                                             \
} while (0)

#define TCGEN05_ALLOC(smem_dst, ncols) \
    asm volatile("tcgen05.alloc.cta_group::1.sync.aligned.shared::cta.b32 [%0], %1;" \
                 :: "r"(smem_dst), "r"(ncols) : "memory")
#define TCGEN05_DEALLOC(tmem, ncols) \
    asm volatile("tcgen05.dealloc.cta_group::1.sync.aligned.b32 %0, %1;" :: "r"(tmem), "r"(ncols))
#define TCGEN05_RELINQUISH() \
    asm volatile("tcgen05.relinquish_alloc_permit.cta_group::1.sync.aligned;")
#define TCGEN05_COMMIT(mbar) \
    asm volatile("tcgen05.commit.cta_group::1.mbarrier::arrive::one.shared::cluster.b64 [%0];" \
                 :: "r"(mbar) : "memory")
#define TCGEN05_FENCE_AFTER() asm volatile("tcgen05.fence::after_thread_sync;" ::: "memory")
#define TCGEN05_FENCE_BEFORE() asm volatile("tcgen05.fence::before_thread_sync;" ::: "memory")
#define TCGEN05_WAIT_LD() asm volatile("tcgen05.wait::ld.sync.aligned;" ::: "memory")

#define TCGEN05_LD_32X32B_X32(r, tmem_addr) \
    asm volatile( \
        "tcgen05.ld.sync.aligned.32x32b.x32.b32 " \
        "{%0, %1, %2, %3, %4, %5, %6, %7, " \
        " %8, %9, %10, %11, %12, %13, %14, %15, " \
        " %16, %17, %18, %19, %20, %21, %22, %23, " \
        " %24, %25, %26, %27, %28, %29, %30, %31}, [%32];" \
        : "=r"((r)[0]),  "=r"((r)[1]),  "=r"((r)[2]),  "=r"((r)[3]), \
          "=r"((r)[4]),  "=r"((r)[5]),  "=r"((r)[6]),  "=r"((r)[7]), \
          "=r"((r)[8]),  "=r"((r)[9]),  "=r"((r)[10]), "=r"((r)[11]), \
          "=r"((r)[12]), "=r"((r)[13]), "=r"((r)[14]), "=r"((r)[15]), \
          "=r"((r)[16]), "=r"((r)[17]), "=r"((r)[18]), "=r"((r)[19]), \
          "=r"((r)[20]), "=r"((r)[21]), "=r"((r)[22]), "=r"((r)[23]), \
          "=r"((r)[24]), "=r"((r)[25]), "=r"((r)[26]), "=r"((r)[27]), \
          "=r"((r)[28]), "=r"((r)[29]), "=r"((r)[30]), "=r"((r)[31]) \
        : "r"(tmem_addr))

// SW128 descriptor: version=1, LBO=1, SBO=64
static __device__ __forceinline__ unsigned long long make_desc(uint32_t addr) {
    const unsigned long long base =
        (2ull << 61) | (1ull << 46) | (64ull << 32) | (1ull << 16);
    return base | ((unsigned long long)(addr >> 4) & 0x3FFFull);
}

// idesc: D=F32(1@4), A=TF32(2@7), B=TF32(2@10), N/8@17, M/16@24
#define TC_IDESC ((1u << 4) | (2u << 7) | (2u << 10) | ((NT / 8) << 17) | ((MT / 16) << 24))

__device__ __forceinline__ void mma_tf32_ss(uint32_t d, unsigned long long ad,
                                            unsigned long long bd, uint32_t en) {
    asm volatile(
        "{\n\t.reg .pred p;\n\t"
        "setp.ne.u32 p, %5, 0;\n\t"
        "tcgen05.mma.cta_group::1.kind::tf32 [%0], %1, %2, %3, {%4, %4, %4, %4}, p;\n\t}"
        :: "r"(d), "l"(ad), "l"(bd), "r"((uint32_t)TC_IDESC), "r"(0u), "r"(en)
        : "memory");
}

#endif  // __CUDA_ARCH_FEAT_SM103_ALL

// ------------------------- small kernels -------------------------
__global__ void init_kernel() {
    int i = blockIdx.x * blockDim.x + threadIdx.x;
    if (i < M_ROWS) g_best[i] = ~0ull;
}

__device__ __forceinline__ void split4(const float4 v, float4& h, float4& l) {
    h.x = __uint_as_float(__float_as_uint(v.x) & 0xFFFFE000u); l.x = tf32_rna(v.x - h.x);
    h.y = __uint_as_float(__float_as_uint(v.y) & 0xFFFFE000u); l.y = tf32_rna(v.y - h.y);
    h.z = __uint_as_float(__float_as_uint(v.z) & 0xFFFFE000u); l.z = tf32_rna(v.z - h.z);
    h.w = __uint_as_float(__float_as_uint(v.w) & 0xFFFFE000u); l.w = tf32_rna(v.w - h.w);
}

__global__ void split_z_kernel(const float* __restrict__ src) {
    int i = blockIdx.x * blockDim.x + threadIdx.x;
    float4 v = ((const float4*)src)[i];
    float4 h, l;
    split4(v, h, l);
    ((float4*)g_zhi)[i] = h;
    ((float4*)g_zlo)[i] = l;
}

__global__ void split_e_kernel(const float* __restrict__ src) {
    int i = blockIdx.x * blockDim.x + threadIdx.x;
    float4 v = ((const float4*)src)[i];
    float4 h, l;
    split4(v, h, l);
    ((float4*)g_ehi)[i] = h;
    ((float4*)g_elo)[i] = l;
}

__global__ void enorm_kernel(const float* __restrict__ emb) {
    int row = blockIdx.x * (blockDim.x >> 5) + (threadIdx.x >> 5);
    int lane = threadIdx.x & 31;
    if (row >= N_CODES) return;
    const float* e = emb + (size_t)row * KDIM;
    float s = 0.f;
#pragma unroll
    for (int c = lane; c < KDIM; c += 32) {
        float v = e[c];
        s = fmaf(v, v, s);
    }
#pragma unroll
    for (int o = 16; o; o >>= 1) s += __shfl_xor_sync(0xffffffffu, s, o);
    if (lane == 0) g_enorm[row] = s;
}

// ------------------------- main GEMM+argmin (dual body) -------------------------
__global__ void __launch_bounds__(256, 2) vq_gemm_kernel() {
    extern __shared__ __align__(1024) char smem[];
    const int tid = threadIdx.x;
    const int bm = blockIdx.y * MT;
    const int bn = blockIdx.x * NT;

#if defined(__CUDA_ARCH_FEAT_SM103_ALL)
    // ================= tcgen05 tf32 path =================
    const uint32_t sb = smem_u32(smem);
    if (tid < 32) {
        TCGEN05_ALLOC(sb, 128);
        TCGEN05_RELINQUISH();
    }
    if (tid == 0) {
        MBARRIER_INIT(sb + TC_MBAR_OFF + 0, 1);
        MBARRIER_INIT(sb + TC_MBAR_OFF + 8, 1);
        MBARRIER_INIT(sb + TC_MBAR_OFF + 16, 1);
    }
    if (tid < NT) ((float*)(smem + TC_EN_OFF))[tid] = g_enorm[bn + tid];
    __syncthreads();

    uint32_t tmem_base;
    asm volatile("ld.shared.b32 %0, [%1];" : "=r"(tmem_base) : "r"(sb));

    auto load_stage = [&](int s) {
        int p = s >> 3;
        int k0 = (s & 7) * BK;
        const float* asrc = (p == 2) ? g_zlo : g_zhi;
        const float* bsrc = (p == 1) ? g_elo : g_ehi;
        uint32_t abase = sb + TC_STAGE0 + (uint32_t)(s % STAGES) * TC_STAGE_BYTES;
        uint32_t bbase = abase + 16384u;
#pragma unroll
        for (int t = 0; t < 4; t++) {
            int idx = tid + t * 256;
            int row = idx >> 3;
            int ch = idx & 7;
            uint32_t off = (uint32_t)(row * 128 + ch * 16);
            uint32_t sw = off ^ ((off >> 3) & 0x70u);
            cp16(abase + sw, asrc + (size_t)(bm + row) * KDIM + k0 + ch * 4);
        }
#pragma unroll
        for (int t = 0; t < 4; t++) {
            int idx = tid + t * 256;
            int row = idx >> 3;
            int ch = idx & 7;
            uint32_t off = (uint32_t)(row * 128 + ch * 16);
            uint32_t sw = off ^ ((off >> 3) & 0x70u);
            cp16(bbase + sw, bsrc + (size_t)(bn + row) * KDIM + k0 + ch * 4);
        }
        cp_commit();
    };

    load_stage(0);
    load_stage(1);

    for (int s = 0; s < CHUNKS; s++) {
        const int buf = s % STAGES;
        if (s == CHUNKS - 1) cp_wait0(); else cp_wait1();
        asm volatile("fence.proxy.async.shared::cta;" ::: "memory");
        __syncthreads();

        if (tid < 32) {
            if (elect_one()) {
                uint32_t abase = sb + TC_STAGE0 + (uint32_t)buf * TC_STAGE_BYTES;
                unsigned long long ad = make_desc(abase);
                unsigned long long bd = make_desc(abase + 16384u);
#pragma unroll
                for (int ks = 0; ks < 4; ks++) {
                    uint32_t en = (s == 0 && ks == 0) ? 0u : 1u;
                    mma_tf32_ss(tmem_base, ad + ks * 2, bd + ks * 2, en);
                }
                TCGEN05_COMMIT(sb + TC_MBAR_OFF + buf * 8);
            }
        }

        if (s + 2 < CHUNKS) {
            if (s >= 1) {
                int sp = s - 1;  // buf (s+2)%3 was last used by stage s-1
                MBARRIER_WAIT_PARITY(sb + TC_MBAR_OFF + ((sp % STAGES) * 8),
                                     (uint32_t)((sp / STAGES) & 1));
            }
            load_stage(s + 2);
        }
    }
    {
        int sp = CHUNKS - 1;
        MBARRIER_WAIT_PARITY(sb + TC_MBAR_OFF + ((sp % STAGES) * 8),
                             (uint32_t)((sp / STAGES) & 1));
    }
    TCGEN05_FENCE_AFTER();
    __syncthreads();

    // epilogue: warp w -> rows (w&3)*32, cols (w>>2)*64
    {
        const int w = tid >> 5;
        const int sub = w & 3;
        const int half = w >> 2;
        const int lane = tid & 31;
        const float* en_sm = (const float*)(smem + TC_EN_OFF);
        const int mrow = bm + sub * 32 + lane;
        unsigned long long best = ~0ull;
#pragma unroll
        for (int c0 = 0; c0 < 64; c0 += 32) {
            uint32_t r[32];
            TCGEN05_LD_32X32B_X32(r, tmem_base + half * 64 + c0);
            TCGEN05_WAIT_LD();
#pragma unroll
            for (int j = 0; j < 32; j++) {
                int nl = half * 64 + c0 + j;
                float d = en_sm[nl] - 2.0f * __uint_as_float(r[j]);
                unsigned long long key =
                    ((unsigned long long)fkey(d) << 32) | (unsigned)(bn + nl);
                best = umin64(best, key);
            }
        }
        atomicMin(&g_best[mrow], best);
    }
    TCGEN05_FENCE_BEFORE();
    __syncthreads();
    if (tid < 32) TCGEN05_DEALLOC(tmem_base, 128);

#else
    // ================= mma.sync tf32 fallback path =================
    const uint32_t sb = smem_u32(smem);
    float* en_sm = (float*)smem;
    if (tid < NT) en_sm[tid] = g_enorm[bn + tid];

    const int w = tid >> 5;
    const int lane = tid & 31;
    const int g = lane >> 2;
    const int t4 = lane & 3;
    const int wm = w >> 2;   // 0..1
    const int wn = w & 3;    // 0..3

    float acc[4][4][4];
#pragma unroll
    for (int i = 0; i < 4; i++)
#pragma unroll
        for (int j = 0; j < 4; j++)
#pragma unroll
            for (int c = 0; c < 4; c++) acc[i][j][c] = 0.f;

    auto load_stage = [&](int s) {
        int p = s >> 3;
        int k0 = (s & 7) * BK;
        const float* asrc = (p == 2) ? g_zlo : g_zhi;
        const float* bsrc = (p == 1) ? g_elo : g_ehi;
        uint32_t abase = sb + FB_STAGE0 + (uint32_t)(s % STAGES) * FB_STAGE_BYTES;
        uint32_t bbase = abase + (uint32_t)(FB_TILE_FLOATS * 4);
#pragma unroll
        for (int t = 0; t < 4; t++) {
            int idx = tid + t * 256;
            int row = idx >> 3;
            int ch = idx & 7;
            cp16(abase + (uint32_t)((row * FB_LDA + ch * 4) * 4),
                 asrc + (size_t)(bm + row) * KDIM + k0 + ch * 4);
        }
#pragma unroll
        for (int t = 0; t < 4; t++) {
            int idx = tid + t * 256;
            int row = idx >> 3;
            int ch = idx & 7;
            cp16(bbase + (uint32_t)((row * FB_LDA + ch * 4) * 4),
                 bsrc + (size_t)(bn + row) * KDIM + k0 + ch * 4);
        }
        cp_commit();
    };

    load_stage(0);
    load_stage(1);

    for (int s = 0; s < CHUNKS; s++) {
        const int buf = s % STAGES;
        if (s == CHUNKS - 1) cp_wait0(); else cp_wait1();
        __syncthreads();
        if (s + 2 < CHUNKS) load_stage(s + 2);

        const float* A = (const float*)(smem + FB_STAGE0 + (size_t)buf * FB_STAGE_BYTES);
        const float* B = A + FB_TILE_FLOATS;
        const float* Abase = A + (wm * 64 + g) * FB_LDA + t4;
        const float* Bbase = B + (wn * 32 + g) * FB_LDA + t4;

#pragma unroll
        for (int ks = 0; ks < 4; ks++) {
            uint32_t a[4][4];
#pragma unroll
            for (int i = 0; i < 4; i++) {
                const float* ab = Abase + i * 16 * FB_LDA + ks * 8;
                a[i][0] = __float_as_uint(ab[0]);
                a[i][1] = __float_as_uint(ab[8 * FB_LDA]);
                a[i][2] = __float_as_uint(ab[4]);
                a[i][3] = __float_as_uint(ab[8 * FB_LDA + 4]);
            }
            uint32_t b[4][2];
#pragma unroll
            for (int j = 0; j < 4; j++) {
                const float* bb = Bbase + j * 8 * FB_LDA + ks * 8;
                b[j][0] = __float_as_uint(bb[0]);
                b[j][1] = __float_as_uint(bb[4]);
            }
#pragma unroll
            for (int i = 0; i < 4; i++)
#pragma unroll
                for (int j = 0; j < 4; j++) {
                    asm("mma.sync.aligned.m16n8k8.row.col.f32.tf32.tf32.f32 "
                        "{%0,%1,%2,%3},{%4,%5,%6,%7},{%8,%9},{%0,%1,%2,%3};"
                        : "+f"(acc[i][j][0]), "+f"(acc[i][j][1]),
                          "+f"(acc[i][j][2]), "+f"(acc[i][j][3])
                        : "r"(a[i][0]), "r"(a[i][1]), "r"(a[i][2]), "r"(a[i][3]),
                          "r"(b[j][0]), "r"(b[j][1]));
                }
        }
        __syncthreads();
    }

    // epilogue
#pragma unroll
    for (int i = 0; i < 4; i++) {
        int r0 = bm + wm * 64 + i * 16 + g;
        unsigned long long k0 = ~0ull, k1 = ~0ull;
#pragma unroll
        for (int j = 0; j < 4; j++) {
            int nl = wn * 32 + j * 8 + t4 * 2;
            float d;
            unsigned long long key;
            d = en_sm[nl] - 2.f * acc[i][j][0];
            key = ((unsigned long long)fkey(d) << 32) | (unsigned)(bn + nl);
            k0 = umin64(k0, key);
            d = en_sm[nl + 1] - 2.f * acc[i][j][1];
            key = ((unsigned long long)fkey(d) << 32) | (unsigned)(bn + nl + 1);
            k0 = umin64(k0, key);
            d = en_sm[nl] - 2.f * acc[i][j][2];
            key = ((unsigned long long)fkey(d) << 32) | (unsigned)(bn + nl);
            k1 = umin64(k1, key);
            d = en_sm[nl + 1] - 2.f * acc[i][j][3];
            key = ((unsigned long long)fkey(d) << 32) | (unsigned)(bn + nl + 1);
            k1 = umin64(k1, key);
        }
        k0 = umin64(k0, __shfl_xor_sync(0xffffffffu, k0, 1));
        k0 = umin64(k0, __shfl_xor_sync(0xffffffffu, k0, 2));
        k1 = umin64(k1, __shfl_xor_sync(0xffffffffu, k1, 1));
        k1 = umin64(k1, __shfl_xor_sync(0xffffffffu, k1, 2));
        if (t4 == 0) {
            atomicMin(&g_best[r0], k0);
            atomicMin(&g_best[r0 + 8], k1);
        }
    }
#endif
}

// ------------------------- gather + loss -------------------------
__global__ void gather_kernel(const float* __restrict__ z,
                              const float* __restrict__ emb,
                              float* __restrict__ out, int has_extra) {
    int row = blockIdx.x;
    int tid = threadIdx.x;
    unsigned long long key = g_best[row];
    int idx = (int)(key & 0xFFFFFFFFull);

    float q = emb[(size_t)idx * KDIM + tid];
    float zv = z[(size_t)row * KDIM + tid];
    out[(size_t)row * KDIM + tid] = q;

    float dfl = q - zv;
    __shared__ float sh[256];
    sh[tid] = dfl * dfl;
    __syncthreads();
#pragma unroll
    for (int o = 128; o; o >>= 1) {
        if (tid < o) sh[tid] += sh[tid + o];
        __syncthreads();
    }
    if (tid == 0) {
        g_partial[row] = sh[0];
        if (has_extra) out[Q_ELEMS + 1 + row] = (float)idx;
    }
}

__global__ void finalize_kernel(float* __restrict__ out, int has_extra) {
    if (!has_extra) return;
    __shared__ float sh[256];
    int tid = threadIdx.x;
    float s = 0.f;
    for (int i = tid; i < M_ROWS; i += 256) s += g_partial[i];
    sh[tid] = s;
    __syncthreads();
#pragma unroll
    for (int o = 128; o; o >>= 1) {
        if (tid < o) sh[tid] += sh[tid + o];
        __syncthreads();
    }
    if (tid == 0) out[Q_ELEMS] = 1.25f * sh[0] / (float)Q_ELEMS;
}

// ------------------------- launcher -------------------------
extern "C" void kernel_launch(void* const* d_in, const int* in_sizes, int n_in,
                              void* d_out, int out_size) {
    const float* z;
    const float* emb;
    if (in_sizes[0] == M_ROWS * KDIM) {
        z = (const float*)d_in[0];
        emb = (const float*)d_in[1];
    } else {
        z = (const float*)d_in[1];
        emb = (const float*)d_in[0];
    }
    float* out = (float*)d_out;
    int has_extra = (out_size >= Q_ELEMS + 1 + M_ROWS) ? 1 : 0;

    cudaFuncSetAttribute(vq_gemm_kernel,
                         cudaFuncAttributeMaxDynamicSharedMemorySize, SMEM_LAUNCH);

    init_kernel<<<M_ROWS / 256, 256>>>();
    split_z_kernel<<<Q_ELEMS / 4 / 256, 256>>>(z);
    split_e_kernel<<<N_CODES * KDIM / 4 / 256, 256>>>(emb);
    enorm_kernel<<<N_CODES / 8, 256>>>(emb);

    dim3 grid(N_CODES / NT, M_ROWS / MT);  // (64, 128)
    vq_gemm_kernel<<<grid, 256, SMEM_LAUNCH>>>();

    gather_kernel<<<M_ROWS, 256>>>(z, emb, out, has_extra);
    finalize_kernel<<<1, 256>>>(out, has_extra);
}